// round 8
// baseline (speedup 1.0000x reference)
#include <cuda_runtime.h>
#include <math.h>

#define Bsz 256
#define Xd  256
#define Hd  512
#define Rd  128
#define Md  128
#define Td  256
#define XHD 768      // X+H
#define CATD 896     // X+H+R
#define NPRE 2176    // R+4H columns of W_full
#define NG1 640      // R+H
#define ODIM 640

typedef unsigned long long ull;

// persistent state / scratch (device globals; no allocation)
__device__ float g_c[Bsz*Hd];
__device__ float g_hmem[Bsz*Md*Rd];
__device__ float g_cc [Bsz*CATD];   // unscaled concat [x, c, h_entry]
__device__ float g_cc2[Bsz*CATD];   // scaled concat
__device__ float g_hent[Bsz*Rd];
__device__ int   g_sel[Bsz];
__device__ float g_fcwxT[Xd*Md];    // fc_w x-part transposed (k-major)
__device__ float g_wcomb[Hd*256];   // [k][0:128]=fc_w c-part^T, [k][128:256]=trans_w^T
__device__ float g_xh[Td*Bsz*Md];   // precomputed x-part of head (+fc_b)

__device__ __forceinline__ float sigf(float v){ return 1.0f/(1.0f+expf(-v)); }
__device__ __forceinline__ ull pack2(float v){ ull r; asm("mov.b64 %0, {%1, %1};" : "=l"(r) : "f"(v)); return r; }
__device__ __forceinline__ void ffma2(ull &d, ull a, ull b){ asm("fma.rn.f32x2 %0, %1, %2, %0;" : "+l"(d) : "l"(a), "l"(b)); }
__device__ __forceinline__ float2 unpk(ull v){ float2 f; asm("mov.b64 {%0, %1}, %2;" : "=f"(f.x), "=f"(f.y) : "l"(v)); return f; }

// ---------------- init: transposes + combined weights + c0 + hmem0 ----------------
__global__ void k_init(const float* __restrict__ fc_w, const float* __restrict__ trans_w,
                       const float* __restrict__ c_bias, const float* __restrict__ hmem_bias)
{
    int idx = blockIdx.x*blockDim.x + threadIdx.x;
    if (idx < Bsz*Md*Rd) g_hmem[idx] = hmem_bias[idx & (Md*Rd-1)];
    if (idx < Bsz*Hd)    g_c[idx] = tanhf(c_bias[idx & (Hd-1)]);
    if (idx < Xd*Md) {               // fcwxT[k][m] = fc_w[m][k], k<256
        int k = idx >> 7, m = idx & 127;
        g_fcwxT[idx] = fc_w[m*XHD + k];
    }
    if (idx < Hd*256) {              // wcomb[k][c]
        int k = idx >> 8, c = idx & 255;
        g_wcomb[idx] = (c < 128) ? fc_w[c*XHD + Xd + k]
                                 : trans_w[(c-128)*Hd + k];
    }
}

// ---------------- Xh precompute: (T*B,128) = x(T*B,256) @ fcwxT + fc_b -------------
__global__ __launch_bounds__(256) void k_xhead(const float* __restrict__ x,
                                               const float* __restrict__ fc_b)
{
    __shared__ __align__(16) float As[16][68];
    __shared__ __align__(16) float Bs[16][128];
    const int tid = threadIdx.x;
    const int rb = blockIdx.x * 64;
    const int tm = tid >> 5;        // 0..7 rows group of 8
    const int tn = tid & 31;        // 0..31 cols group of 4 (2 pairs)

    ull acc[8][2] = {};

    const int ar = tid >> 2, akq = tid & 3;
    const float* Ap = x + (size_t)(rb + ar)*Xd + akq*4;
    const int bk = tid >> 4, bm = tid & 15;
    const float* Bp = g_fcwxT + (size_t)bk*Md + bm*8;

    float4 pa = *(const float4*)Ap;
    float4 pb0 = *(const float4*)(Bp);
    float4 pb1 = *(const float4*)(Bp + 4);

    for (int kt = 0; kt < Xd/16; kt++) {
        As[akq*4+0][ar]=pa.x; As[akq*4+1][ar]=pa.y; As[akq*4+2][ar]=pa.z; As[akq*4+3][ar]=pa.w;
        *(float4*)&Bs[bk][bm*8]   = pb0;
        *(float4*)&Bs[bk][bm*8+4] = pb1;
        __syncthreads();
        if (kt+1 < Xd/16) {
            int k0 = (kt+1)*16;
            pa  = *(const float4*)(Ap + k0);
            pb0 = *(const float4*)(Bp + (size_t)k0*Md);
            pb1 = *(const float4*)(Bp + (size_t)k0*Md + 4);
        }
        #pragma unroll
        for (int kk = 0; kk < 16; kk++) {
            float4 a0 = *(const float4*)&As[kk][tm*8];
            float4 a1 = *(const float4*)&As[kk][tm*8+4];
            ulonglong2 bq = *(const ulonglong2*)&Bs[kk][tn*4];
            float a_[8] = {a0.x,a0.y,a0.z,a0.w,a1.x,a1.y,a1.z,a1.w};
            #pragma unroll
            for (int i=0;i<8;i++){
                ull ap = pack2(a_[i]);
                ffma2(acc[i][0], ap, bq.x);
                ffma2(acc[i][1], ap, bq.y);
            }
        }
        __syncthreads();
    }
    float4 fb = *(const float4*)(fc_b + tn*4);
    #pragma unroll
    for (int i=0;i<8;i++){
        int row = rb + tm*8 + i;
        float2 l0 = unpk(acc[i][0]), l1 = unpk(acc[i][1]);
        float4 o = { l0.x+fb.x, l0.y+fb.y, l1.x+fb.z, l1.y+fb.w };
        *(float4*)(g_xh + (size_t)row*Md + tn*4) = o;
    }
}

// ---------------- gates1 GEMM: cc(256x896) @ W1(896x640), fused sigmoid -> cc2 ------
// BM=32, BN=64, full K=896, 256 threads, thread tile 2x4 (f32x2). grid (8,10)=80.
__global__ __launch_bounds__(256) void k_gates(const float* __restrict__ W1,
                                               const float* __restrict__ bias1)
{
    __shared__ __align__(16) float As[2][16][34];
    __shared__ __align__(16) float Bs[2][16][64];
    const int tid = threadIdx.x;
    const int rb = blockIdx.x * 32;
    const int nb = blockIdx.y * 64;
    const int tm = tid >> 4;       // 0..15, rows tm*2, tm*2+1
    const int tn = tid & 15;       // cols tn*4 (2 pairs)

    ull acc[2][2] = {};

    const int ar = tid >> 2, akq = tid & 3;            // tid<128 loads A
    const float* Ap = g_cc + (size_t)(rb + ar)*CATD + akq*4;
    const int bk = tid >> 4, bn4 = tid & 15;           // 16x16 = 256 loads B
    const float* Bp = W1 + (size_t)bk*NG1 + nb + bn4*4;

    float4 pa = {0,0,0,0};
    if (tid < 128) pa = *(const float4*)Ap;
    float4 pb = *(const float4*)Bp;

    if (tid < 128){
        As[0][akq*4+0][ar]=pa.x; As[0][akq*4+1][ar]=pa.y;
        As[0][akq*4+2][ar]=pa.z; As[0][akq*4+3][ar]=pa.w;
    }
    *(float4*)&Bs[0][bk][bn4*4] = pb;
    __syncthreads();

    for (int kt = 0; kt < CATD/16; kt++) {
        const int p = kt & 1;
        if (kt+1 < CATD/16) {
            int k0 = (kt+1)*16;
            if (tid < 128) pa = *(const float4*)(Ap + k0);
            pb = *(const float4*)(Bp + (size_t)k0*NG1);
        }
        #pragma unroll
        for (int kk = 0; kk < 16; kk++) {
            float2 a2 = *(const float2*)&As[p][kk][tm*2];
            ulonglong2 bq = *(const ulonglong2*)&Bs[p][kk][tn*4];
            ull a0 = pack2(a2.x), a1 = pack2(a2.y);
            ffma2(acc[0][0], a0, bq.x); ffma2(acc[0][1], a0, bq.y);
            ffma2(acc[1][0], a1, bq.x); ffma2(acc[1][1], a1, bq.y);
        }
        if (kt+1 < CATD/16) {
            const int q = p^1;
            if (tid < 128){
                As[q][akq*4+0][ar]=pa.x; As[q][akq*4+1][ar]=pa.y;
                As[q][akq*4+2][ar]=pa.z; As[q][akq*4+3][ar]=pa.w;
            }
            *(float4*)&Bs[q][bk][bn4*4] = pb;
        }
        __syncthreads();
    }
    const int n0 = nb + tn*4;
    float4 bv = *(const float4*)(bias1 + n0);
    #pragma unroll
    for (int i=0;i<2;i++){
        int row = rb + tm*2 + i;
        float2 l0 = unpk(acc[i][0]), l1 = unpk(acc[i][1]);
        float4 ccv = *(const float4*)(g_cc + (size_t)row*CATD + Xd + n0);
        float4 o;
        o.x = ccv.x * sigf(l0.x + bv.x);
        o.y = ccv.y * sigf(l0.y + bv.y);
        o.z = ccv.z * sigf(l1.x + bv.z);
        o.w = ccv.w * sigf(l1.y + bv.w);
        *(float4*)(g_cc2 + (size_t)row*CATD + Xd + n0) = o;
    }
}

// ---------------- big GEMM with fused LSTM / r epilogue (f32x2) ---------------------
// 256 threads, 64 rows x 16 quads, thread tile 4x4, double-buffered. grid (4,34).
__global__ __launch_bounds__(256) void k_big(const float* __restrict__ Wf,
                                             const float* __restrict__ bias,
                                             float* __restrict__ out, int t)
{
    __shared__ __align__(16) float As[2][16][68];
    __shared__ __align__(16) float Bs[2][16][64];
    const int tid = threadIdx.x;
    const int rb = blockIdx.x * 64;
    const int y = blockIdx.y;
    const bool isOm = (y >= 32);
    const int cb = isOm ? (2048 + (y-32)*64) : y*16;
    const int S  = isOm ? 16 : 512;
    const int tm = tid >> 4;   // rows group of 4
    const int tx = tid & 15;   // quad index

    ull acc[4][2] = {};

    const int ar = tid >> 2, akq = tid & 3;
    const float* Ap = g_cc2 + (size_t)(rb + ar)*CATD + akq*4;
    const int bk = tid >> 4, bg = (tid >> 2) & 3, bq4 = tid & 3;
    const float* Bp = Wf + (size_t)bk*NPRE + cb + S*bg + bq4*4;

    float4 pa = *(const float4*)Ap;
    float4 pb = *(const float4*)Bp;

    As[0][akq*4+0][ar]=pa.x; As[0][akq*4+1][ar]=pa.y;
    As[0][akq*4+2][ar]=pa.z; As[0][akq*4+3][ar]=pa.w;
    Bs[0][bk][(bq4*4+0)*4+bg]=pb.x; Bs[0][bk][(bq4*4+1)*4+bg]=pb.y;
    Bs[0][bk][(bq4*4+2)*4+bg]=pb.z; Bs[0][bk][(bq4*4+3)*4+bg]=pb.w;
    __syncthreads();

    for (int kt = 0; kt < CATD/16; kt++) {
        const int p = kt & 1;
        if (kt+1 < CATD/16) {
            int k0 = (kt+1)*16;
            pa = *(const float4*)(Ap + k0);
            pb = *(const float4*)(Bp + (size_t)k0*NPRE);
        }
        #pragma unroll
        for (int kk=0; kk<16; kk++){
            float4 av = *(const float4*)&As[p][kk][tm*4];
            ulonglong2 bq = *(const ulonglong2*)&Bs[p][kk][tx*4];
            ull a0 = pack2(av.x), a1 = pack2(av.y), a2 = pack2(av.z), a3 = pack2(av.w);
            ffma2(acc[0][0], a0, bq.x); ffma2(acc[0][1], a0, bq.y);
            ffma2(acc[1][0], a1, bq.x); ffma2(acc[1][1], a1, bq.y);
            ffma2(acc[2][0], a2, bq.x); ffma2(acc[2][1], a2, bq.y);
            ffma2(acc[3][0], a3, bq.x); ffma2(acc[3][1], a3, bq.y);
        }
        if (kt+1 < CATD/16) {
            const int q = p^1;
            As[q][akq*4+0][ar]=pa.x; As[q][akq*4+1][ar]=pa.y;
            As[q][akq*4+2][ar]=pa.z; As[q][akq*4+3][ar]=pa.w;
            Bs[q][bk][(bq4*4+0)*4+bg]=pb.x; Bs[q][bk][(bq4*4+1)*4+bg]=pb.y;
            Bs[q][bk][(bq4*4+2)*4+bg]=pb.z; Bs[q][bk][(bq4*4+3)*4+bg]=pb.w;
        }
        __syncthreads();
    }

    if (!isOm) {
        const int n = cb + tx;
        const float bi = bias[n], bj = bias[n+512], bf = bias[n+1024], bo = bias[n+1536];
        #pragma unroll
        for (int i=0;i<4;i++){
            int row = rb + tm*4 + i;
            float2 ij = unpk(acc[i][0]), fo = unpk(acc[i][1]);
            float c_old = g_c[row*Hd + n];
            float iv = ij.x+bi, jv = ij.y+bj, fv = fo.x+bf, ov = fo.y+bo;
            float nc = tanhf(c_old*sigf(fv + 1.0f) + sigf(iv)*tanhf(jv));
            g_c[row*Hd + n] = nc;
            out[(size_t)t*Bsz*ODIM + (size_t)row*ODIM + n] = nc * sigf(ov);
        }
    } else {
        #pragma unroll
        for (int i=0;i<4;i++){
            int row = rb + tm*4 + i;
            float2 g01 = unpk(acc[i][0]), g23 = unpk(acc[i][1]);
            float gv[4] = {g01.x, g01.y, g23.x, g23.y};
            #pragma unroll
            for (int g=0; g<4; g++){
                int mcol = (cb - 2048) + 16*g + tx;
                float rv = g_hent[row*Rd + mcol] * sigf(gv[g] + bias[2048 + mcol]);
                out[(size_t)t*Bsz*ODIM + (size_t)row*ODIM + Hd + mcol] = rv;
            }
        }
    }
}

// ---------------- tail: [head_c | wv] GEMM (K=512) + argmax + hmem scatter + gather
// grid 64 blocks x 256 threads; 4 batch rows per block. t in [-1, T-2].
__global__ __launch_bounds__(256) void k_tail(const float* __restrict__ x,
                                              const float* __restrict__ noise,
                                              const float* __restrict__ trans_b,
                                              int t)
{
    __shared__ float s_c[4][512];
    __shared__ float s_head[4][132];
    __shared__ float s_wv[4][132];
    __shared__ int   s_sel[4], s_selold[4];
    const int tid = threadIdx.x;
    const int warp = tid >> 5, lane = tid & 31;
    const int b0 = blockIdx.x * 4;
    const int tn = t + 1;

    #pragma unroll
    for (int j=0;j<2;j++){ int i = tid + 256*j; int r = i>>7, cc = i&127;
      *(float4*)&s_c[r][cc*4] = *(const float4*)(g_c + (b0+r)*Hd + cc*4); }
    if (tid < 4) s_selold[tid] = g_sel[b0+tid];
    __syncthreads();

    // GEMM: 4 rows x 256 cols (128 head_c | 128 wv), K=512 from s_c
    {
        const int rg = tid >> 6;          // 0..3 row
        const int c4 = (tid & 63) * 4;    // col group
        ull acc0 = 0, acc1 = 0;
        const float* wp = g_wcomb + c4;
        #pragma unroll 4
        for (int k = 0; k < Hd; k++){
            ull ap = pack2(s_c[rg][k]);
            ulonglong2 wq = *(const ulonglong2*)(wp + (size_t)k*256);
            ffma2(acc0, ap, wq.x);
            ffma2(acc1, ap, wq.y);
        }
        float2 l0 = unpk(acc0), l1 = unpk(acc1);
        float4 a = { l0.x, l0.y, l1.x, l1.y };
        if (c4 < 128) {
            float4 xh = *(const float4*)(g_xh + ((size_t)tn*Bsz + b0 + rg)*Md + c4);
            a.x += xh.x; a.y += xh.y; a.z += xh.z; a.w += xh.w;
            *(float4*)&s_head[rg][c4] = a;
        } else {
            int m4 = c4 - 128;
            float4 tb = *(const float4*)(trans_b + m4);
            a.x += tb.x; a.y += tb.y; a.z += tb.z; a.w += tb.w;
            *(float4*)&s_wv[rg][m4] = a;
        }
    }
    __syncthreads();

    // warps 0-3: gumbel + argmax; warps 4-7: hmem row write (t>=0)
    if (warp < 4) {
        int r = warp;
        float4 hv = *(const float4*)&s_head[r][lane*4];
        float4 nz = *(const float4*)(noise + ((size_t)tn*Bsz + b0 + r)*Md + lane*4);
        float v[4];
        v[0] = hv.x - logf(1e-20f - logf(1e-20f + nz.x));
        v[1] = hv.y - logf(1e-20f - logf(1e-20f + nz.y));
        v[2] = hv.z - logf(1e-20f - logf(1e-20f + nz.z));
        v[3] = hv.w - logf(1e-20f - logf(1e-20f + nz.w));
        float best = v[0]; int bi = lane*4;
        #pragma unroll
        for (int c=1;c<4;c++) if (v[c] > best){ best = v[c]; bi = lane*4+c; }
        #pragma unroll
        for (int off=16; off; off>>=1){
            float ov = __shfl_xor_sync(0xffffffffu, best, off);
            int   oi = __shfl_xor_sync(0xffffffffu, bi,   off);
            if (ov > best || (ov == best && oi < bi)){ best = ov; bi = oi; }
        }
        if (lane == 0) s_sel[r] = bi;
    } else if (t >= 0) {
        int r = warp - 4;
        float4 wv = *(const float4*)&s_wv[r][lane*4];
        int idx = (t < Md) ? t : s_selold[r];
        *(float4*)(g_hmem + ((size_t)(b0+r)*Md + idx)*Rd + lane*4) = wv;
    }
    __syncthreads();

    // gather h_entry for t+1, write cc / cc2 / sel
    if (warp < 4) {
        int r = warp;
        int sel = s_sel[r];
        float4 h4 = *(const float4*)(g_hmem + ((size_t)(b0+r)*Md + sel)*Rd + lane*4);
        *(float4*)(g_hent + (b0+r)*Rd + lane*4) = h4;
        *(float4*)(g_cc + (size_t)(b0+r)*CATD + XHD + lane*4) = h4;
        if (lane == 0) g_sel[b0+r] = sel;
    }
    { int r = tid>>6, cc = tid&63;
      float4 xv = *(const float4*)(x + ((size_t)tn*Bsz + b0 + r)*Xd + cc*4);
      *(float4*)(g_cc  + (size_t)(b0+r)*CATD + cc*4) = xv;
      *(float4*)(g_cc2 + (size_t)(b0+r)*CATD + cc*4) = xv; }
    #pragma unroll
    for (int j=0;j<2;j++){ int i = tid + 256*j; int r = i>>7, cc = i&127;
      *(float4*)(g_cc + (size_t)(b0+r)*CATD + Xd + cc*4) = *(const float4*)&s_c[r][cc*4]; }
}

extern "C" void kernel_launch(void* const* d_in, const int* in_sizes, int n_in,
                              void* d_out, int out_size)
{
    const float* x       = (const float*)d_in[0];
    const float* noise   = (const float*)d_in[1];
    const float* W_full  = (const float*)d_in[2];
    const float* bias    = (const float*)d_in[3];
    const float* W_full1 = (const float*)d_in[4];
    const float* bias1   = (const float*)d_in[5];
    const float* fc_w    = (const float*)d_in[6];
    const float* fc_b    = (const float*)d_in[7];
    const float* trans_w = (const float*)d_in[8];
    const float* trans_b = (const float*)d_in[9];
    const float* c_bias  = (const float*)d_in[10];
    const float* hmem_b  = (const float*)d_in[11];
    float* out = (float*)d_out;

    const int initN = Bsz*Md*Rd;
    k_init<<<(initN + 255)/256, 256>>>(fc_w, trans_w, c_bias, hmem_b);
    k_xhead<<<Td*Bsz/64, 256>>>(x, fc_b);
    k_tail<<<64, 256>>>(x, noise, trans_b, -1);   // prologue: head/argmax for t=0
    for (int t = 0; t < Td; t++){
        k_gates<<<dim3(8,10), 256>>>(W_full1, bias1);
        k_big  <<<dim3(4,34), 256>>>(W_full, bias, out, t);
        if (t < Td-1) k_tail<<<64, 256>>>(x, noise, trans_b, t);
    }
}

// round 9
// speedup vs baseline: 1.5670x; 1.5670x over previous
#include <cuda_runtime.h>
#include <math.h>

#define Bsz 256
#define Xd  256
#define Hd  512
#define Rd  128
#define Md  128
#define Td  256
#define XHD 768      // X+H
#define CATD 896     // X+H+R
#define NPRE 2176    // R+4H columns of W_full
#define NG1 640      // R+H
#define ODIM 640
#define GRID 148

typedef unsigned long long ull;

// persistent state / scratch (device globals; no allocation)
__device__ float g_c[Bsz*Hd];
__device__ float g_hmem[Bsz*Md*Rd];
__device__ float g_hent[Bsz*Rd];
__device__ int   g_sel[Bsz];
__device__ float g_fcwxT[Xd*Md];     // fc_w x-part transposed (k-major)
__device__ float g_wcomb[Hd*256];    // [k][0:128]=fc_w c-part^T, [k][128:256]=trans_w^T
__device__ float g_xh[Td*Bsz*Md];    // precomputed x-part of head (+fc_b)
__device__ float g_cc2s[Bsz*NG1];    // scaled [c|hent] part of concat
__device__ float g_g1p8[8][Bsz*NG1]; // gates1 K-chunk partials
__device__ float g_tp[8][Bsz*256];   // tail GEMM split-K partials

// grid barrier state
__device__ unsigned g_bar_arrive;
__device__ volatile unsigned g_bar_gen;

__device__ __forceinline__ float sigf(float v){ return 1.0f/(1.0f+expf(-v)); }
__device__ __forceinline__ ull pack2(float v){ ull r; asm("mov.b64 %0, {%1, %1};" : "=l"(r) : "f"(v)); return r; }
__device__ __forceinline__ void ffma2(ull &d, ull a, ull b){ asm("fma.rn.f32x2 %0, %1, %2, %0;" : "+l"(d) : "l"(a), "l"(b)); }
__device__ __forceinline__ float2 unpk(ull v){ float2 f; asm("mov.b64 {%0, %1}, %2;" : "=f"(f.x), "=f"(f.y) : "l"(v)); return f; }
__device__ __forceinline__ float4 ld4(const float* p){ return *(const float4*)p; }

__device__ __forceinline__ void gridbar()
{
    __threadfence();
    __syncthreads();
    if (threadIdx.x == 0){
        unsigned gen = g_bar_gen;
        if (atomicAdd(&g_bar_arrive, 1u) == GRID-1u){
            g_bar_arrive = 0u;
            __threadfence();
            g_bar_gen = gen + 1u;
        } else {
            while (g_bar_gen == gen) { }
            __threadfence();
        }
    }
    __syncthreads();
}

// A-tile element loads (piecewise concat, boundaries are multiples of 16)
__device__ __forceinline__ float4 loadA_cat(const float* __restrict__ x, int t, int row, int kg)
{
    const float* p;
    if (kg < Xd)       p = x + ((size_t)t*Bsz + row)*Xd + kg;
    else if (kg < XHD) p = g_c + (size_t)row*Hd + (kg - Xd);
    else               p = g_hent + (size_t)row*Rd + (kg - XHD);
    return *(const float4*)p;
}
__device__ __forceinline__ float4 loadA_cc2(const float* __restrict__ x, int t, int row, int kg)
{
    const float* p = (kg < Xd) ? (x + ((size_t)t*Bsz + row)*Xd + kg)
                               : (g_cc2s + (size_t)row*NG1 + (kg - Xd));
    return *(const float4*)p;
}

// ---------------- init: transposes + combined weights + c0 + hmem0 + barrier reset --
__global__ void k_init(const float* __restrict__ fc_w, const float* __restrict__ trans_w,
                       const float* __restrict__ c_bias, const float* __restrict__ hmem_bias)
{
    int idx = blockIdx.x*blockDim.x + threadIdx.x;
    if (idx == 0){ g_bar_arrive = 0u; g_bar_gen = 0u; }
    if (idx < Bsz*Md*Rd) g_hmem[idx] = hmem_bias[idx & (Md*Rd-1)];
    if (idx < Bsz*Hd)    g_c[idx] = tanhf(c_bias[idx & (Hd-1)]);
    if (idx < Xd*Md){ int k = idx >> 7, m = idx & 127; g_fcwxT[idx] = fc_w[m*XHD + k]; }
    if (idx < Hd*256){
        int k = idx >> 8, c = idx & 255;
        g_wcomb[idx] = (c < 128) ? fc_w[c*XHD + Xd + k] : trans_w[(c-128)*Hd + k];
    }
}

// ---------------- Xh precompute: (T*B,128) = x(T*B,256) @ fcwxT + fc_b --------------
__global__ __launch_bounds__(256) void k_xhead(const float* __restrict__ x,
                                               const float* __restrict__ fc_b)
{
    __shared__ __align__(16) float As[16][68];
    __shared__ __align__(16) float Bs[16][128];
    const int tid = threadIdx.x;
    const int rb = blockIdx.x * 64;
    const int tm = tid >> 5;
    const int tn = tid & 31;

    ull acc[8][2] = {};

    const int ar = tid >> 2, akq = tid & 3;
    const float* Ap = x + (size_t)(rb + ar)*Xd + akq*4;
    const int bk = tid >> 4, bm = tid & 15;
    const float* Bp = g_fcwxT + (size_t)bk*Md + bm*8;

    float4 pa = ld4(Ap);
    float4 pb0 = ld4(Bp);
    float4 pb1 = ld4(Bp + 4);

    for (int kt = 0; kt < Xd/16; kt++) {
        As[akq*4+0][ar]=pa.x; As[akq*4+1][ar]=pa.y; As[akq*4+2][ar]=pa.z; As[akq*4+3][ar]=pa.w;
        *(float4*)&Bs[bk][bm*8]   = pb0;
        *(float4*)&Bs[bk][bm*8+4] = pb1;
        __syncthreads();
        if (kt+1 < Xd/16) {
            int k0 = (kt+1)*16;
            pa  = ld4(Ap + k0);
            pb0 = ld4(Bp + (size_t)k0*Md);
            pb1 = ld4(Bp + (size_t)k0*Md + 4);
        }
        #pragma unroll
        for (int kk = 0; kk < 16; kk++) {
            float4 a0 = *(const float4*)&As[kk][tm*8];
            float4 a1 = *(const float4*)&As[kk][tm*8+4];
            ulonglong2 bq = *(const ulonglong2*)&Bs[kk][tn*4];
            float a_[8] = {a0.x,a0.y,a0.z,a0.w,a1.x,a1.y,a1.z,a1.w};
            #pragma unroll
            for (int i=0;i<8;i++){
                ull ap = pack2(a_[i]);
                ffma2(acc[i][0], ap, bq.x);
                ffma2(acc[i][1], ap, bq.y);
            }
        }
        __syncthreads();
    }
    float4 fb = ld4(fc_b + tn*4);
    #pragma unroll
    for (int i=0;i<8;i++){
        int row = rb + tm*8 + i;
        float2 l0 = unpk(acc[i][0]), l1 = unpk(acc[i][1]);
        float4 o = { l0.x+fb.x, l0.y+fb.y, l1.x+fb.z, l1.y+fb.w };
        *(float4*)(g_xh + (size_t)row*Md + tn*4) = o;
    }
}

// =========================== persistent-kernel phases ===============================

// G1: gates1 partials. 640 units of (32 rows x 64 cols x K112). grid-strided.
__device__ void phG1(float* SM, const float* __restrict__ x,
                     const float* __restrict__ W1, int t, int bid, int tid)
{
    float (*As)[16][34] = (float(*)[16][34])SM;
    float (*Bs)[16][64] = (float(*)[16][64])(SM + 2*16*34);
    const int tm = tid >> 4, tn = tid & 15;
    const int ar = tid >> 2, akq = tid & 3;
    const int bk = tid >> 4, bn4 = tid & 15;

    for (int u = bid; u < 640; u += GRID){
        const int tile = u >> 3, z = u & 7;
        const int rb = (tile / 10) * 32;
        const int nb = (tile % 10) * 64;
        const int kbase = z * 112;

        ull acc00=0, acc01=0, acc10=0, acc11=0;
        const float* Bp = W1 + (size_t)(kbase + bk)*NG1 + nb + bn4*4;

        float4 pa, pb;
        if (tid < 128) pa = loadA_cat(x, t, rb + ar, kbase + akq*4);
        pb = ld4(Bp);
        if (tid < 128){
            As[0][akq*4+0][ar]=pa.x; As[0][akq*4+1][ar]=pa.y;
            As[0][akq*4+2][ar]=pa.z; As[0][akq*4+3][ar]=pa.w;
        }
        *(float4*)&Bs[0][bk][bn4*4] = pb;
        __syncthreads();

        for (int kt = 0; kt < 7; kt++){
            const int p = kt & 1;
            if (kt < 6){
                int k0 = (kt+1)*16;
                if (tid < 128) pa = loadA_cat(x, t, rb + ar, kbase + k0 + akq*4);
                pb = ld4(Bp + (size_t)k0*NG1);
            }
            #pragma unroll
            for (int kk = 0; kk < 16; kk++){
                float2 a2 = *(const float2*)&As[p][kk][tm*2];
                ulonglong2 bq = *(const ulonglong2*)&Bs[p][kk][tn*4];
                ull a0 = pack2(a2.x), a1 = pack2(a2.y);
                ffma2(acc00,a0,bq.x); ffma2(acc01,a0,bq.y);
                ffma2(acc10,a1,bq.x); ffma2(acc11,a1,bq.y);
            }
            if (kt < 6){
                const int q = p^1;
                if (tid < 128){
                    As[q][akq*4+0][ar]=pa.x; As[q][akq*4+1][ar]=pa.y;
                    As[q][akq*4+2][ar]=pa.z; As[q][akq*4+3][ar]=pa.w;
                }
                *(float4*)&Bs[q][bk][bn4*4] = pb;
            }
            __syncthreads();
        }
        float* op = g_g1p8[z];
        {
            float2 l0 = unpk(acc00), l1 = unpk(acc01);
            float4 o = { l0.x, l0.y, l1.x, l1.y };
            *(float4*)(op + (size_t)(rb + tm*2)*NG1 + nb + tn*4) = o;
        }
        {
            float2 l0 = unpk(acc10), l1 = unpk(acc11);
            float4 o = { l0.x, l0.y, l1.x, l1.y };
            *(float4*)(op + (size_t)(rb + tm*2 + 1)*NG1 + nb + tn*4) = o;
        }
    }
}

// G2: combine 8 K-chunk partials, sigmoid-scale [c|hent] -> g_cc2s
__device__ void phG2(const float* __restrict__ bias1, int bid, int tid)
{
    for (int idx = bid*256 + tid; idx < Bsz*160; idx += GRID*256){
        int row = idx / 160;
        int c = (idx - row*160) * 4;
        size_t o = (size_t)row*NG1 + c;
        float4 s = ld4(g_g1p8[0] + o);
        #pragma unroll
        for (int z = 1; z < 8; z++){
            float4 p = ld4(g_g1p8[z] + o);
            s.x += p.x; s.y += p.y; s.z += p.z; s.w += p.w;
        }
        float4 b = ld4(bias1 + c);
        float4 cv = (c < Hd) ? ld4(g_c + (size_t)row*Hd + c)
                             : ld4(g_hent + (size_t)row*Rd + (c - Hd));
        float4 r;
        r.x = cv.x * sigf(s.x + b.x);
        r.y = cv.y * sigf(s.y + b.y);
        r.z = cv.z * sigf(s.z + b.z);
        r.w = cv.w * sigf(s.w + b.w);
        *(float4*)(g_cc2s + o) = r;
    }
}

// Big: 136 tiles (64 rows x 16 quad-cols) full K=896, fused LSTM / r epilogue
__device__ void phBig(float* SM, const float* __restrict__ x,
                      const float* __restrict__ Wf, const float* __restrict__ bias,
                      float* __restrict__ out, int t, int bid, int tid)
{
    if (bid >= 136) return;
    float (*As)[16][68] = (float(*)[16][68])SM;
    float (*Bs)[16][64] = (float(*)[16][64])(SM + 2*16*68);
    const int rb = (bid & 3) * 64;
    const int y  = bid >> 2;
    const bool isOm = (y >= 32);
    const int cb = isOm ? (2048 + (y-32)*64) : y*16;
    const int S  = isOm ? 16 : 512;
    const int tm = tid >> 4;
    const int tx = tid & 15;

    ull acc[4][2] = {};

    const int ar = tid >> 2, akq = tid & 3;
    const int bk = tid >> 4, bg = (tid >> 2) & 3, bq4 = tid & 3;
    const float* Bp = Wf + (size_t)bk*NPRE + cb + S*bg + bq4*4;

    float4 pa = loadA_cc2(x, t, rb + ar, akq*4);
    float4 pb = ld4(Bp);

    As[0][akq*4+0][ar]=pa.x; As[0][akq*4+1][ar]=pa.y;
    As[0][akq*4+2][ar]=pa.z; As[0][akq*4+3][ar]=pa.w;
    Bs[0][bk][(bq4*4+0)*4+bg]=pb.x; Bs[0][bk][(bq4*4+1)*4+bg]=pb.y;
    Bs[0][bk][(bq4*4+2)*4+bg]=pb.z; Bs[0][bk][(bq4*4+3)*4+bg]=pb.w;
    __syncthreads();

    for (int kt = 0; kt < CATD/16; kt++){
        const int p = kt & 1;
        if (kt+1 < CATD/16){
            int k0 = (kt+1)*16;
            pa = loadA_cc2(x, t, rb + ar, k0 + akq*4);
            pb = ld4(Bp + (size_t)k0*NPRE);
        }
        #pragma unroll
        for (int kk = 0; kk < 16; kk++){
            float4 av = *(const float4*)&As[p][kk][tm*4];
            ulonglong2 bq = *(const ulonglong2*)&Bs[p][kk][tx*4];
            ull a0=pack2(av.x), a1=pack2(av.y), a2=pack2(av.z), a3=pack2(av.w);
            ffma2(acc[0][0],a0,bq.x); ffma2(acc[0][1],a0,bq.y);
            ffma2(acc[1][0],a1,bq.x); ffma2(acc[1][1],a1,bq.y);
            ffma2(acc[2][0],a2,bq.x); ffma2(acc[2][1],a2,bq.y);
            ffma2(acc[3][0],a3,bq.x); ffma2(acc[3][1],a3,bq.y);
        }
        if (kt+1 < CATD/16){
            const int q = p^1;
            As[q][akq*4+0][ar]=pa.x; As[q][akq*4+1][ar]=pa.y;
            As[q][akq*4+2][ar]=pa.z; As[q][akq*4+3][ar]=pa.w;
            Bs[q][bk][(bq4*4+0)*4+bg]=pb.x; Bs[q][bk][(bq4*4+1)*4+bg]=pb.y;
            Bs[q][bk][(bq4*4+2)*4+bg]=pb.z; Bs[q][bk][(bq4*4+3)*4+bg]=pb.w;
        }
        __syncthreads();
    }

    if (!isOm){
        const int n = cb + tx;
        const float bi = bias[n], bj = bias[n+512], bf = bias[n+1024], bo = bias[n+1536];
        #pragma unroll
        for (int i = 0; i < 4; i++){
            int row = rb + tm*4 + i;
            float2 ij = unpk(acc[i][0]), fo = unpk(acc[i][1]);
            float c_old = g_c[row*Hd + n];
            float iv = ij.x+bi, jv = ij.y+bj, fv = fo.x+bf, ov = fo.y+bo;
            float nc = tanhf(c_old*sigf(fv + 1.0f) + sigf(iv)*tanhf(jv));
            g_c[row*Hd + n] = nc;
            out[(size_t)t*Bsz*ODIM + (size_t)row*ODIM + n] = nc * sigf(ov);
        }
    } else {
        #pragma unroll
        for (int i = 0; i < 4; i++){
            int row = rb + tm*4 + i;
            float2 g01 = unpk(acc[i][0]), g23 = unpk(acc[i][1]);
            float gv[4] = {g01.x, g01.y, g23.x, g23.y};
            #pragma unroll
            for (int g = 0; g < 4; g++){
                int mcol = (cb - 2048) + 16*g + tx;
                float rv = g_hent[row*Rd + mcol] * sigf(gv[g] + bias[2048 + mcol]);
                out[(size_t)t*Bsz*ODIM + (size_t)row*ODIM + Hd + mcol] = rv;
            }
        }
    }
}

// T1: tail GEMM partials: new_c(256x512) @ wcomb(512x256), 128 units 64x64xK64
__device__ void phT1(float* SM, int bid, int tid)
{
    if (bid >= 128) return;
    float (*As)[16][68] = (float(*)[16][68])SM;
    float (*Bs)[16][64] = (float(*)[16][64])(SM + 2*16*68);
    const int rb = (bid & 3) * 64;
    const int nb = ((bid >> 2) & 3) * 64;
    const int zk = (bid >> 4) * 64;
    const int tm = tid >> 4, tn = tid & 15;

    ull acc[4][2] = {};

    const int ar = tid >> 2, akq = tid & 3;
    const float* Ap = g_c + (size_t)(rb + ar)*Hd + zk + akq*4;
    const int bk = tid >> 4, bn4 = tid & 15;
    const float* Bp = g_wcomb + (size_t)(zk + bk)*256 + nb + bn4*4;

    float4 pa = ld4(Ap);
    float4 pb = ld4(Bp);

    As[0][akq*4+0][ar]=pa.x; As[0][akq*4+1][ar]=pa.y;
    As[0][akq*4+2][ar]=pa.z; As[0][akq*4+3][ar]=pa.w;
    *(float4*)&Bs[0][bk][bn4*4] = pb;
    __syncthreads();

    for (int kt = 0; kt < 4; kt++){
        const int p = kt & 1;
        if (kt+1 < 4){
            int k0 = (kt+1)*16;
            pa = ld4(Ap + k0);
            pb = ld4(Bp + (size_t)k0*256);
        }
        #pragma unroll
        for (int kk = 0; kk < 16; kk++){
            float4 av = *(const float4*)&As[p][kk][tm*4];
            ulonglong2 bq = *(const ulonglong2*)&Bs[p][kk][tn*4];
            ull a0=pack2(av.x), a1=pack2(av.y), a2=pack2(av.z), a3=pack2(av.w);
            ffma2(acc[0][0],a0,bq.x); ffma2(acc[0][1],a0,bq.y);
            ffma2(acc[1][0],a1,bq.x); ffma2(acc[1][1],a1,bq.y);
            ffma2(acc[2][0],a2,bq.x); ffma2(acc[2][1],a2,bq.y);
            ffma2(acc[3][0],a3,bq.x); ffma2(acc[3][1],a3,bq.y);
        }
        if (kt+1 < 4){
            const int q = p^1;
            As[q][akq*4+0][ar]=pa.x; As[q][akq*4+1][ar]=pa.y;
            As[q][akq*4+2][ar]=pa.z; As[q][akq*4+3][ar]=pa.w;
            *(float4*)&Bs[q][bk][bn4*4] = pb;
        }
        __syncthreads();
    }
    float* op = g_tp[bid >> 4];
    #pragma unroll
    for (int i = 0; i < 4; i++){
        int row = rb + tm*4 + i;
        float2 l0 = unpk(acc[i][0]), l1 = unpk(acc[i][1]);
        float4 o = { l0.x, l0.y, l1.x, l1.y };
        *(float4*)(op + (size_t)row*256 + nb + tn*4) = o;
    }
}

// T2: combine partials + gumbel/argmax + hmem scatter(t) + gather(t+1)
__device__ void phT2(float* SM, int* SI, const float* __restrict__ noise,
                     const float* __restrict__ trans_b, int t, int bid, int tid)
{
    if (bid >= 64) return;
    float (*s_head)[132] = (float(*)[132])SM;
    float (*s_wv)[132]   = (float(*)[132])(SM + 4*132);
    int* s_sel = SI; int* s_selold = SI + 4;
    const int warp = tid >> 5, lane = tid & 31;
    const int b0 = bid * 4;
    const int tn = t + 1;

    if (tid < 4) s_selold[tid] = g_sel[b0 + tid];
    {
        const int rg = tid >> 6;
        const int c4 = (tid & 63) * 4;
        size_t off = (size_t)(b0 + rg)*256 + c4;
        float4 a = ld4(g_tp[0] + off);
        #pragma unroll
        for (int z = 1; z < 8; z++){
            float4 p = ld4(g_tp[z] + off);
            a.x += p.x; a.y += p.y; a.z += p.z; a.w += p.w;
        }
        if (c4 < 128){
            float4 xh = ld4(g_xh + ((size_t)tn*Bsz + b0 + rg)*Md + c4);
            a.x += xh.x; a.y += xh.y; a.z += xh.z; a.w += xh.w;
            *(float4*)&s_head[rg][c4] = a;
        } else {
            float4 tb = ld4(trans_b + (c4 - 128));
            a.x += tb.x; a.y += tb.y; a.z += tb.z; a.w += tb.w;
            *(float4*)&s_wv[rg][c4 - 128] = a;
        }
    }
    __syncthreads();

    if (warp < 4){
        int r = warp;
        float4 hv = *(const float4*)&s_head[r][lane*4];
        float4 nz = ld4(noise + ((size_t)tn*Bsz + b0 + r)*Md + lane*4);
        float v[4];
        v[0] = hv.x - logf(1e-20f - logf(1e-20f + nz.x));
        v[1] = hv.y - logf(1e-20f - logf(1e-20f + nz.y));
        v[2] = hv.z - logf(1e-20f - logf(1e-20f + nz.z));
        v[3] = hv.w - logf(1e-20f - logf(1e-20f + nz.w));
        float best = v[0]; int bi = lane*4;
        #pragma unroll
        for (int c = 1; c < 4; c++) if (v[c] > best){ best = v[c]; bi = lane*4 + c; }
        #pragma unroll
        for (int off = 16; off; off >>= 1){
            float ov = __shfl_xor_sync(0xffffffffu, best, off);
            int   oi = __shfl_xor_sync(0xffffffffu, bi,   off);
            if (ov > best || (ov == best && oi < bi)){ best = ov; bi = oi; }
        }
        if (lane == 0) s_sel[r] = bi;
    } else if (t >= 0){
        int r = warp - 4;
        float4 wv = *(const float4*)&s_wv[r][lane*4];
        int idx = (t < Md) ? t : s_selold[r];
        *(float4*)(g_hmem + ((size_t)(b0+r)*Md + idx)*Rd + lane*4) = wv;
    }
    __syncthreads();

    if (warp < 4){
        int r = warp;
        int sel = s_sel[r];
        float4 h4 = ld4(g_hmem + ((size_t)(b0+r)*Md + sel)*Rd + lane*4);
        *(float4*)(g_hent + (size_t)(b0+r)*Rd + lane*4) = h4;
        if (lane == 0) g_sel[b0+r] = sel;
    }
}

// ---------------- persistent kernel: the whole scan ----------------
__global__ __launch_bounds__(256, 1) void k_persist(
    const float* __restrict__ x, const float* __restrict__ noise,
    const float* __restrict__ Wf, const float* __restrict__ bias,
    const float* __restrict__ W1, const float* __restrict__ bias1,
    const float* __restrict__ trans_b, float* __restrict__ out)
{
    __shared__ __align__(16) float SM[4352];
    __shared__ int SI[8];
    const int tid = threadIdx.x, bid = blockIdx.x;

    // prologue: head/argmax for t=0 (wv side unused at t=-1)
    phT1(SM, bid, tid);                              gridbar();
    phT2(SM, SI, noise, trans_b, -1, bid, tid);      gridbar();

    for (int t = 0; t < Td; t++){
        phG1(SM, x, W1, t, bid, tid);                gridbar();
        phG2(bias1, bid, tid);                       gridbar();
        phBig(SM, x, Wf, bias, out, t, bid, tid);    gridbar();
        if (t < Td - 1){
            phT1(SM, bid, tid);                      gridbar();
            phT2(SM, SI, noise, trans_b, t, bid, tid); gridbar();
        }
    }
}

extern "C" void kernel_launch(void* const* d_in, const int* in_sizes, int n_in,
                              void* d_out, int out_size)
{
    const float* x       = (const float*)d_in[0];
    const float* noise   = (const float*)d_in[1];
    const float* W_full  = (const float*)d_in[2];
    const float* bias    = (const float*)d_in[3];
    const float* W_full1 = (const float*)d_in[4];
    const float* bias1   = (const float*)d_in[5];
    const float* fc_w    = (const float*)d_in[6];
    const float* fc_b    = (const float*)d_in[7];
    const float* trans_w = (const float*)d_in[8];
    const float* trans_b = (const float*)d_in[9];
    const float* c_bias  = (const float*)d_in[10];
    const float* hmem_b  = (const float*)d_in[11];
    float* out = (float*)d_out;

    const int initN = Bsz*Md*Rd;
    k_init<<<(initN + 255)/256, 256>>>(fc_w, trans_w, c_bias, hmem_b);
    k_xhead<<<Td*Bsz/64, 256>>>(x, fc_b);
    k_persist<<<GRID, 256>>>(x, noise, W_full, bias, W_full1, bias1, trans_b, out);
}

// round 10
// speedup vs baseline: 1.9731x; 1.2591x over previous
#include <cuda_runtime.h>
#include <math.h>

#define Bsz 256
#define Xd  256
#define Hd  512
#define Rd  128
#define Md  128
#define Td  256
#define XHD 768      // X+H
#define CATD 896     // X+H+R
#define NPRE 2176    // R+4H columns of W_full
#define NG1 640      // R+H
#define ODIM 640
#define GRID 148

typedef unsigned long long ull;

// persistent state / scratch (device globals; no allocation)
__device__ float g_c[Bsz*Hd];
__device__ float g_hmem[Bsz*Md*Rd];
__device__ float g_hent[Bsz*Rd];
__device__ int   g_sel[Bsz];
__device__ float g_fcwxT[Xd*Md];      // fc_w x-part transposed (k-major)
__device__ float g_wcomb[Hd*256];     // [k][0:128]=fc_w c-part^T, [k][128:256]=trans_w^T
__device__ float g_xh[Td*Bsz*Md];     // precomputed x-part of head (+fc_b)
__device__ float g_cc2s[Bsz*NG1];     // scaled [c|hent] part of concat
__device__ float g_g1p[14][Bsz*NG1];  // gates1 K-chunk partials
__device__ float g_prep[4][Bsz*NPRE]; // big GEMM K-chunk partials
__device__ float g_tp[32][Bsz*256];   // tail GEMM K-chunk partials

// grid barrier state
__device__ unsigned g_bar_arrive;
__device__ volatile unsigned g_bar_gen;

__device__ __forceinline__ float sigf(float v){ return 1.0f/(1.0f+expf(-v)); }
__device__ __forceinline__ ull pack2(float v){ ull r; asm("mov.b64 %0, {%1, %1};" : "=l"(r) : "f"(v)); return r; }
__device__ __forceinline__ void ffma2(ull &d, ull a, ull b){ asm("fma.rn.f32x2 %0, %1, %2, %0;" : "+l"(d) : "l"(a), "l"(b)); }
__device__ __forceinline__ float2 unpk(ull v){ float2 f; asm("mov.b64 {%0, %1}, %2;" : "=f"(f.x), "=f"(f.y) : "l"(v)); return f; }
__device__ __forceinline__ float4 ld4(const float* p){ return *(const float4*)p; }

__device__ __forceinline__ void gridbar()
{
    __threadfence();
    __syncthreads();
    if (threadIdx.x == 0){
        unsigned gen = g_bar_gen;
        if (atomicAdd(&g_bar_arrive, 1u) == GRID-1u){
            g_bar_arrive = 0u;
            __threadfence();
            g_bar_gen = gen + 1u;
        } else {
            while (g_bar_gen == gen) { }
            __threadfence();
        }
    }
    __syncthreads();
}

// ---------------- init ----------------
__global__ void k_init(const float* __restrict__ fc_w, const float* __restrict__ trans_w,
                       const float* __restrict__ c_bias, const float* __restrict__ hmem_bias)
{
    int idx = blockIdx.x*blockDim.x + threadIdx.x;
    if (idx == 0){ g_bar_arrive = 0u; g_bar_gen = 0u; }
    if (idx < Bsz*Md*Rd) g_hmem[idx] = hmem_bias[idx & (Md*Rd-1)];
    if (idx < Bsz*Hd)    g_c[idx] = tanhf(c_bias[idx & (Hd-1)]);
    if (idx < Xd*Md){ int k = idx >> 7, m = idx & 127; g_fcwxT[idx] = fc_w[m*XHD + k]; }
    if (idx < Hd*256){
        int k = idx >> 8, c = idx & 255;
        g_wcomb[idx] = (c < 128) ? fc_w[c*XHD + Xd + k] : trans_w[(c-128)*Hd + k];
    }
}

// ---------------- Xh precompute ----------------
__global__ __launch_bounds__(256) void k_xhead(const float* __restrict__ x,
                                               const float* __restrict__ fc_b)
{
    __shared__ __align__(16) float As[16][68];
    __shared__ __align__(16) float Bs[16][128];
    const int tid = threadIdx.x;
    const int rb = blockIdx.x * 64;
    const int tm = tid >> 5;
    const int tn = tid & 31;

    ull acc[8][2] = {};

    const int ar = tid >> 2, akq = tid & 3;
    const float* Ap = x + (size_t)(rb + ar)*Xd + akq*4;
    const int bk = tid >> 4, bm = tid & 15;
    const float* Bp = g_fcwxT + (size_t)bk*Md + bm*8;

    float4 pa = ld4(Ap);
    float4 pb0 = ld4(Bp);
    float4 pb1 = ld4(Bp + 4);

    for (int kt = 0; kt < Xd/16; kt++) {
        As[akq*4+0][ar]=pa.x; As[akq*4+1][ar]=pa.y; As[akq*4+2][ar]=pa.z; As[akq*4+3][ar]=pa.w;
        *(float4*)&Bs[bk][bm*8]   = pb0;
        *(float4*)&Bs[bk][bm*8+4] = pb1;
        __syncthreads();
        if (kt+1 < Xd/16) {
            int k0 = (kt+1)*16;
            pa  = ld4(Ap + k0);
            pb0 = ld4(Bp + (size_t)k0*Md);
            pb1 = ld4(Bp + (size_t)k0*Md + 4);
        }
        #pragma unroll
        for (int kk = 0; kk < 16; kk++) {
            float4 a0 = *(const float4*)&As[kk][tm*8];
            float4 a1 = *(const float4*)&As[kk][tm*8+4];
            ulonglong2 bq = *(const ulonglong2*)&Bs[kk][tn*4];
            float a_[8] = {a0.x,a0.y,a0.z,a0.w,a1.x,a1.y,a1.z,a1.w};
            #pragma unroll
            for (int i=0;i<8;i++){
                ull ap = pack2(a_[i]);
                ffma2(acc[i][0], ap, bq.x);
                ffma2(acc[i][1], ap, bq.y);
            }
        }
        __syncthreads();
    }
    float4 fb = ld4(fc_b + tn*4);
    #pragma unroll
    for (int i=0;i<8;i++){
        int row = rb + tm*8 + i;
        float2 l0 = unpk(acc[i][0]), l1 = unpk(acc[i][1]);
        float4 o = { l0.x+fb.x, l0.y+fb.y, l1.x+fb.z, l1.y+fb.w };
        *(float4*)(g_xh + (size_t)row*Md + tn*4) = o;
    }
}

// ============ unified 128x128 GEMM unit (8x8 thread tile, FFMA2, double-buffered) ====

template<int MODE>
__device__ __forceinline__ float4 loadA(const float* __restrict__ x, int t, int row, int kg)
{
    if (MODE == 0){            // concat [x | c | hent]
        const float* p;
        if (kg < Xd)       p = x + ((size_t)t*Bsz + row)*Xd + kg;
        else if (kg < XHD) p = g_c + (size_t)row*Hd + (kg - Xd);
        else               p = g_hent + (size_t)row*Rd + (kg - XHD);
        return ld4(p);
    } else if (MODE == 1){     // [x | cc2s]
        const float* p = (kg < Xd) ? (x + ((size_t)t*Bsz + row)*Xd + kg)
                                   : (g_cc2s + (size_t)row*NG1 + (kg - Xd));
        return ld4(p);
    } else {                   // g_c
        return ld4(g_c + (size_t)row*Hd + kg);
    }
}

template<int MODE>
__device__ void gemm128(float* SM, const float* __restrict__ x, int t,
                        const float* __restrict__ Bm, int ldb,
                        int rb, int nb, int kbase, int nkt,
                        float* __restrict__ outP, int ldo)
{
    float (*As)[16][132] = (float(*)[16][132])SM;
    float (*Bs)[16][128] = (float(*)[16][128])(SM + 2*16*132);
    const int tid = threadIdx.x;
    const int tm = tid >> 4, tn = tid & 15;
    const int ia0 = tid*2, ia1 = tid*2+1;
    const int ar0 = ia0 >> 2, ak0 = (ia0 & 3)*4;
    const int ar1 = ia1 >> 2, ak1 = (ia1 & 3)*4;
    const int bk0 = ia0 >> 5, bc0 = (ia0 & 31)*4;
    const int bk1 = ia1 >> 5, bc1 = (ia1 & 31)*4;

    ull acc[8][4] = {};

    float4 pa0 = loadA<MODE>(x, t, rb+ar0, kbase + ak0);
    float4 pa1 = loadA<MODE>(x, t, rb+ar1, kbase + ak1);
    float4 pb0 = ld4(Bm + (size_t)(kbase + bk0)*ldb + nb + bc0);
    float4 pb1 = ld4(Bm + (size_t)(kbase + bk1)*ldb + nb + bc1);

    for (int kt = 0; kt < nkt; kt++){
        const int p = kt & 1;
        As[p][ak0+0][ar0]=pa0.x; As[p][ak0+1][ar0]=pa0.y; As[p][ak0+2][ar0]=pa0.z; As[p][ak0+3][ar0]=pa0.w;
        As[p][ak1+0][ar1]=pa1.x; As[p][ak1+1][ar1]=pa1.y; As[p][ak1+2][ar1]=pa1.z; As[p][ak1+3][ar1]=pa1.w;
        *(float4*)&Bs[p][bk0][bc0] = pb0;
        *(float4*)&Bs[p][bk1][bc1] = pb1;
        __syncthreads();
        if (kt+1 < nkt){
            int k0 = kbase + (kt+1)*16;
            pa0 = loadA<MODE>(x, t, rb+ar0, k0 + ak0);
            pa1 = loadA<MODE>(x, t, rb+ar1, k0 + ak1);
            pb0 = ld4(Bm + (size_t)(k0 + bk0)*ldb + nb + bc0);
            pb1 = ld4(Bm + (size_t)(k0 + bk1)*ldb + nb + bc1);
        }
        #pragma unroll
        for (int kk = 0; kk < 16; kk++){
            float4 a0 = *(const float4*)&As[p][kk][tm*8];
            float4 a1 = *(const float4*)&As[p][kk][tm*8+4];
            ulonglong2 b0 = *(const ulonglong2*)&Bs[p][kk][tn*8];
            ulonglong2 b1 = *(const ulonglong2*)&Bs[p][kk][tn*8+4];
            float av[8] = {a0.x,a0.y,a0.z,a0.w,a1.x,a1.y,a1.z,a1.w};
            ull bq[4] = {b0.x,b0.y,b1.x,b1.y};
            #pragma unroll
            for (int r = 0; r < 8; r++){
                ull ap = pack2(av[r]);
                ffma2(acc[r][0], ap, bq[0]);
                ffma2(acc[r][1], ap, bq[1]);
                ffma2(acc[r][2], ap, bq[2]);
                ffma2(acc[r][3], ap, bq[3]);
            }
        }
        __syncthreads();
    }
    #pragma unroll
    for (int r = 0; r < 8; r++){
        float2 c0 = unpk(acc[r][0]), c1 = unpk(acc[r][1]);
        float2 c2 = unpk(acc[r][2]), c3 = unpk(acc[r][3]);
        float* op = outP + (size_t)(rb + tm*8 + r)*ldo + nb + tn*8;
        float4 o0 = {c0.x, c0.y, c1.x, c1.y};
        float4 o1 = {c2.x, c2.y, c3.x, c3.y};
        *(float4*)op = o0;
        *(float4*)(op+4) = o1;
    }
}

// =========================== persistent-kernel phases ===============================

// G1: gates1 partials. 140 units = 10 tiles (128x128) x 14 K-chunks (K64).
__device__ void phG1(float* SM, const float* __restrict__ x,
                     const float* __restrict__ W1, int t, int bid)
{
    if (bid >= 140) return;
    const int tile = bid % 10, z = bid / 10;
    const int rb = (tile / 5) * 128, nb = (tile % 5) * 128;
    gemm128<0>(SM, x, t, W1, NG1, rb, nb, z*64, 4, g_g1p[z], NG1);
}

// G2: combine 14 partials, sigmoid-scale [c|hent] -> g_cc2s
__device__ void phG2(const float* __restrict__ bias1, int bid, int tid)
{
    for (int idx = bid*256 + tid; idx < Bsz*160; idx += GRID*256){
        int row = idx / 160;
        int c = (idx - row*160) * 4;
        size_t o = (size_t)row*NG1 + c;
        float4 s = ld4(g_g1p[0] + o);
        #pragma unroll
        for (int z = 1; z < 14; z++){
            float4 p = ld4(g_g1p[z] + o);
            s.x += p.x; s.y += p.y; s.z += p.z; s.w += p.w;
        }
        float4 b = ld4(bias1 + c);
        float4 cv = (c < Hd) ? ld4(g_c + (size_t)row*Hd + c)
                             : ld4(g_hent + (size_t)row*Rd + (c - Hd));
        float4 r;
        r.x = cv.x * sigf(s.x + b.x);
        r.y = cv.y * sigf(s.y + b.y);
        r.z = cv.z * sigf(s.z + b.z);
        r.w = cv.w * sigf(s.w + b.w);
        *(float4*)(g_cc2s + o) = r;
    }
}

// Big: 136 units = 34 tiles (128x128 plain cols) x 4 K-chunks (K224).
__device__ void phBig(float* SM, const float* __restrict__ x,
                      const float* __restrict__ Wf, int t, int bid)
{
    if (bid >= 136) return;
    const int tile = bid % 34, z = bid / 34;
    const int rb = (tile / 17) * 128, nb = (tile % 17) * 128;
    gemm128<1>(SM, x, t, Wf, NPRE, rb, nb, z*224, 14, g_prep[z], NPRE);
}

// C: combine 4 big partials + LSTM / r epilogue -> g_c, out
__device__ void phC(const float* __restrict__ bias, float* __restrict__ out,
                    int t, int bid, int tid)
{
    for (int idx = bid*256 + tid; idx < Bsz*Hd; idx += GRID*256){
        int row = idx >> 9, n = idx & 511;
        size_t base = (size_t)row*NPRE + n;
        float pi = 0.f, pj = 0.f, pf = 0.f, po = 0.f;
        #pragma unroll
        for (int z = 0; z < 4; z++){
            pi += g_prep[z][base];
            pj += g_prep[z][base+512];
            pf += g_prep[z][base+1024];
            po += g_prep[z][base+1536];
        }
        pi += bias[n]; pj += bias[512+n]; pf += bias[1024+n]; po += bias[1536+n];
        float c_old = g_c[row*Hd + n];
        float nc = tanhf(c_old*sigf(pf + 1.0f) + sigf(pi)*tanhf(pj));
        g_c[row*Hd + n] = nc;
        out[(size_t)t*Bsz*ODIM + (size_t)row*ODIM + n] = nc * sigf(po);
    }
    for (int idx = bid*256 + tid; idx < Bsz*Md; idx += GRID*256){
        int row = idx >> 7, m = idx & 127;
        size_t base = (size_t)row*NPRE + 2048 + m;
        float s = 0.f;
        #pragma unroll
        for (int z = 0; z < 4; z++) s += g_prep[z][base];
        float rv = g_hent[row*Rd + m] * sigf(s + bias[2048 + m]);
        out[(size_t)t*Bsz*ODIM + (size_t)row*ODIM + Hd + m] = rv;
    }
}

// T1: tail GEMM partials. 128 units = 4 tiles (128x128) x 32 K-chunks (K16).
__device__ void phT1(float* SM, int bid)
{
    if (bid >= 128) return;
    const int tile = bid % 4, z = bid / 4;
    const int rb = (tile >> 1) * 128, nb = (tile & 1) * 128;
    gemm128<2>(SM, (const float*)0, 0, g_wcomb, 256, rb, nb, z*16, 1, g_tp[z], 256);
}

// T2: combine 32 partials + gumbel/argmax + hmem scatter(t) + gather(t+1)
__device__ void phT2(float* SM, int* SI, const float* __restrict__ noise,
                     const float* __restrict__ trans_b, int t, int bid, int tid)
{
    if (bid >= 64) return;
    float (*s_head)[132] = (float(*)[132])SM;
    float (*s_wv)[132]   = (float(*)[132])(SM + 4*132);
    int* s_sel = SI; int* s_selold = SI + 4;
    const int warp = tid >> 5, lane = tid & 31;
    const int b0 = bid * 4;
    const int tn = t + 1;

    if (tid < 4) s_selold[tid] = g_sel[b0 + tid];
    {
        const int rg = tid >> 6;
        const int c4 = (tid & 63) * 4;
        size_t off = (size_t)(b0 + rg)*256 + c4;
        float4 a = {0.f,0.f,0.f,0.f};
        #pragma unroll
        for (int z = 0; z < 32; z++){
            float4 p = ld4(g_tp[z] + off);
            a.x += p.x; a.y += p.y; a.z += p.z; a.w += p.w;
        }
        if (c4 < 128){
            float4 xh = ld4(g_xh + ((size_t)tn*Bsz + b0 + rg)*Md + c4);
            a.x += xh.x; a.y += xh.y; a.z += xh.z; a.w += xh.w;
            *(float4*)&s_head[rg][c4] = a;
        } else {
            float4 tb = ld4(trans_b + (c4 - 128));
            a.x += tb.x; a.y += tb.y; a.z += tb.z; a.w += tb.w;
            *(float4*)&s_wv[rg][c4 - 128] = a;
        }
    }
    __syncthreads();

    if (warp < 4){
        int r = warp;
        float4 hv = *(const float4*)&s_head[r][lane*4];
        float4 nz = ld4(noise + ((size_t)tn*Bsz + b0 + r)*Md + lane*4);
        float v[4];
        v[0] = hv.x - logf(1e-20f - logf(1e-20f + nz.x));
        v[1] = hv.y - logf(1e-20f - logf(1e-20f + nz.y));
        v[2] = hv.z - logf(1e-20f - logf(1e-20f + nz.z));
        v[3] = hv.w - logf(1e-20f - logf(1e-20f + nz.w));
        float best = v[0]; int bi = lane*4;
        #pragma unroll
        for (int c = 1; c < 4; c++) if (v[c] > best){ best = v[c]; bi = lane*4 + c; }
        #pragma unroll
        for (int off = 16; off; off >>= 1){
            float ov = __shfl_xor_sync(0xffffffffu, best, off);
            int   oi = __shfl_xor_sync(0xffffffffu, bi,   off);
            if (ov > best || (ov == best && oi < bi)){ best = ov; bi = oi; }
        }
        if (lane == 0) s_sel[r] = bi;
    } else if (t >= 0){
        int r = warp - 4;
        float4 wv = *(const float4*)&s_wv[r][lane*4];
        int idx = (t < Md) ? t : s_selold[r];
        *(float4*)(g_hmem + ((size_t)(b0+r)*Md + idx)*Rd + lane*4) = wv;
    }
    __syncthreads();

    if (warp < 4){
        int r = warp;
        int sel = s_sel[r];
        float4 h4 = ld4(g_hmem + ((size_t)(b0+r)*Md + sel)*Rd + lane*4);
        *(float4*)(g_hent + (size_t)(b0+r)*Rd + lane*4) = h4;
        if (lane == 0) g_sel[b0+r] = sel;
    }
}

// ---------------- persistent kernel: the whole scan ----------------
__global__ __launch_bounds__(256, 1) void k_persist(
    const float* __restrict__ x, const float* __restrict__ noise,
    const float* __restrict__ Wf, const float* __restrict__ bias,
    const float* __restrict__ W1, const float* __restrict__ bias1,
    const float* __restrict__ trans_b, float* __restrict__ out)
{
    __shared__ __align__(16) float SM[8320];   // 33.3 KB: As[2][16][132] + Bs[2][16][128]
    __shared__ int SI[8];
    const int tid = threadIdx.x, bid = blockIdx.x;

    // prologue: head/argmax for t=0
    phT1(SM, bid);                                   gridbar();
    phT2(SM, SI, noise, trans_b, -1, bid, tid);      gridbar();

    for (int t = 0; t < Td; t++){
        phG1(SM, x, W1, t, bid);                     gridbar();
        phG2(bias1, bid, tid);                       gridbar();
        phBig(SM, x, Wf, t, bid);                    gridbar();
        phC(bias, out, t, bid, tid);                 gridbar();
        if (t < Td - 1){
            phT1(SM, bid);                           gridbar();
            phT2(SM, SI, noise, trans_b, t, bid, tid); gridbar();
        }
    }
}

extern "C" void kernel_launch(void* const* d_in, const int* in_sizes, int n_in,
                              void* d_out, int out_size)
{
    const float* x       = (const float*)d_in[0];
    const float* noise   = (const float*)d_in[1];
    const float* W_full  = (const float*)d_in[2];
    const float* bias    = (const float*)d_in[3];
    const float* W_full1 = (const float*)d_in[4];
    const float* bias1   = (const float*)d_in[5];
    const float* fc_w    = (const float*)d_in[6];
    const float* fc_b    = (const float*)d_in[7];
    const float* trans_w = (const float*)d_in[8];
    const float* trans_b = (const float*)d_in[9];
    const float* c_bias  = (const float*)d_in[10];
    const float* hmem_b  = (const float*)d_in[11];
    float* out = (float*)d_out;

    const int initN = Bsz*Md*Rd;
    k_init<<<(initN + 255)/256, 256>>>(fc_w, trans_w, c_bias, hmem_b);
    k_xhead<<<Td*Bsz/64, 256>>>(x, fc_b);
    k_persist<<<GRID, 256>>>(x, noise, W_full, bias, W_full1, bias1, trans_b, out);
}